// round 2
// baseline (speedup 1.0000x reference)
#include <cuda_runtime.h>

#define ZS   512
#define MM   512
#define HHN  511
#define NB   65536

// ---------------- scratch (static device globals; no allocation) ----------------
__device__ float g_vn[HHN * ZS];              // normalized Householder vectors
__device__ float g_q [ZS * MM];               // q = prod(I - 2 v v^T)
__device__ float g_A [ZS * MM];               // A  = q @ r1
__device__ float g_Bt[ZS * MM];               // Bt = q @ r2^T
__device__ float g_rrii[MM];                  // diag(r1)*diag(r2)
__device__ float g_hB[(size_t)NB * MM];       // tanh(z@Bt + c)

typedef unsigned long long u64;

__device__ __forceinline__ u64 fma2(u64 a, u64 b, u64 c) {
    u64 d;
    asm("fma.rn.f32x2 %0, %1, %2, %3;" : "=l"(d) : "l"(a), "l"(b), "l"(c));
    return d;
}
__device__ __forceinline__ void unpack2(u64 p, float& lo, float& hi) {
    asm("mov.b64 {%0, %1}, %2;" : "=f"(lo), "=f"(hi) : "l"(p));
}

// ---------------- init: rrii + zero ldj ----------------
__global__ void init_kernel(const float* __restrict__ Rs,
                            const float* __restrict__ r2diag,
                            float* __restrict__ ldj) {
    int i = blockIdx.x * blockDim.x + threadIdx.x;
    if (i < MM) g_rrii[i] = Rs[(size_t)i * MM + i] * r2diag[i];
    if (i < NB) ldj[i] = 0.f;
}

// ---------------- normalize v rows ----------------
__global__ void normalize_kernel(const float* __restrict__ v) {
    int row = blockIdx.x;           // 0..510
    int tid = threadIdx.x;          // 256 threads
    float a = v[row * ZS + tid];
    float b = v[row * ZS + tid + 256];
    float s = a * a + b * b;
    #pragma unroll
    for (int o = 16; o > 0; o >>= 1) s += __shfl_xor_sync(0xffffffffu, s, o);
    __shared__ float ws[8];
    if ((tid & 31) == 0) ws[tid >> 5] = s;
    __syncthreads();
    float tot = ws[0] + ws[1] + ws[2] + ws[3] + ws[4] + ws[5] + ws[6] + ws[7];
    float inv = rsqrtf(tot);
    g_vn[row * ZS + tid]       = a * inv;
    g_vn[row * ZS + tid + 256] = b * inv;
}

// ---------------- Householder scan: one warp per row of q ----------------
__global__ void __launch_bounds__(256) scan_kernel() {
    __shared__ float sv[2][ZS];
    int tid  = threadIdx.x;
    int lane = tid & 31, warp = tid >> 5;
    int row  = blockIdx.x * 8 + warp;       // 64 blocks * 8 warps = 512 rows
    int base = lane * 16;                   // 16 contiguous cols per lane

    float f[16];
    #pragma unroll
    for (int j = 0; j < 16; j++) f[j] = (base + j == row) ? 1.f : 0.f;

    { // preload v_0
        float2 t = *(const float2*)&g_vn[tid * 2];
        sv[0][tid * 2] = t.x; sv[0][tid * 2 + 1] = t.y;
    }
    __syncthreads();

    for (int i = 0; i < HHN; i++) {
        float2 nx;
        bool pf = (i + 1 < HHN);
        if (pf) nx = *(const float2*)&g_vn[(size_t)(i + 1) * ZS + tid * 2];

        const float*  cv  = sv[i & 1];
        const float4* cv4 = (const float4*)(cv + base);
        float vv[16];
        #pragma unroll
        for (int j4 = 0; j4 < 4; j4++) {
            float4 V = cv4[j4];
            vv[j4*4+0] = V.x; vv[j4*4+1] = V.y; vv[j4*4+2] = V.z; vv[j4*4+3] = V.w;
        }
        float d0 = 0, d1 = 0, d2 = 0, d3 = 0;
        #pragma unroll
        for (int j4 = 0; j4 < 4; j4++) {
            d0 = fmaf(f[j4*4+0], vv[j4*4+0], d0);
            d1 = fmaf(f[j4*4+1], vv[j4*4+1], d1);
            d2 = fmaf(f[j4*4+2], vv[j4*4+2], d2);
            d3 = fmaf(f[j4*4+3], vv[j4*4+3], d3);
        }
        float dot = (d0 + d1) + (d2 + d3);
        #pragma unroll
        for (int o = 16; o > 0; o >>= 1) dot += __shfl_xor_sync(0xffffffffu, dot, o);
        dot *= 2.f;
        #pragma unroll
        for (int j = 0; j < 16; j++) f[j] = fmaf(-dot, vv[j], f[j]);

        if (pf) {
            float* nb = sv[(i + 1) & 1];
            nb[tid * 2] = nx.x; nb[tid * 2 + 1] = nx.y;
        }
        __syncthreads();
    }

    float4* qo = (float4*)&g_q[(size_t)row * ZS + base];
    qo[0] = make_float4(f[0],  f[1],  f[2],  f[3]);
    qo[1] = make_float4(f[4],  f[5],  f[6],  f[7]);
    qo[2] = make_float4(f[8],  f[9],  f[10], f[11]);
    qo[3] = make_float4(f[12], f[13], f[14], f[15]);
}

// ---------------- small GEMMs: A = q@r1 (mode 0), Bt = q@r2^T (mode 1) ----------------
__global__ void __launch_bounds__(256) small_gemm_kernel(const float* __restrict__ Rs,
                                                         const float* __restrict__ r2diag) {
    __shared__ float Qs[16][68];
    __shared__ float Bs[16][68];
    int tid = threadIdx.x;
    int tx = tid & 15, ty = tid >> 4;
    int j0 = blockIdx.x * 64, i0 = blockIdx.y * 64;
    int mode = blockIdx.z;
    float acc[4][4] = {};

    for (int kt = 0; kt < 32; kt++) {
        { // Q tile 64(i) x 16(k), transposed into Qs[k][i]
            int i = tid >> 2, kq = tid & 3;
            float4 qv = *(const float4*)&g_q[(size_t)(i0 + i) * ZS + kt * 16 + kq * 4];
            Qs[kq*4+0][i] = qv.x; Qs[kq*4+1][i] = qv.y;
            Qs[kq*4+2][i] = qv.z; Qs[kq*4+3][i] = qv.w;
        }
        { // B tile 16(k) x 64(j), built on the fly
            int kr = tid >> 4, nq = tid & 15;
            int kg = kt * 16 + kr;
            int jg0 = j0 + nq * 4;
            if (mode == 0) {  // r1[k,j] = (k<=j) ? Rs[k,j] : 0
                float4 bv = *(const float4*)&Rs[(size_t)kg * MM + jg0];
                Bs[kr][nq*4+0] = (kg <= jg0 + 0) ? bv.x : 0.f;
                Bs[kr][nq*4+1] = (kg <= jg0 + 1) ? bv.y : 0.f;
                Bs[kr][nq*4+2] = (kg <= jg0 + 2) ? bv.z : 0.f;
                Bs[kr][nq*4+3] = (kg <= jg0 + 3) ? bv.w : 0.f;
            } else {          // r2^T[k,j] = r2[j,k] = (k>j)?Rs[j,k] : (k==j)?r2diag[j] : 0
                #pragma unroll
                for (int e = 0; e < 4; e++) {
                    int jg = jg0 + e;
                    float val;
                    if      (kg >  jg) val = Rs[(size_t)jg * MM + kg];
                    else if (kg == jg) val = r2diag[jg];
                    else               val = 0.f;
                    Bs[kr][nq*4+e] = val;
                }
            }
        }
        __syncthreads();
        #pragma unroll
        for (int kk = 0; kk < 16; kk++) {
            float a[4], b[4];
            #pragma unroll
            for (int e = 0; e < 4; e++) { a[e] = Qs[kk][ty*4+e]; b[e] = Bs[kk][tx*4+e]; }
            #pragma unroll
            for (int x = 0; x < 4; x++)
                #pragma unroll
                for (int y = 0; y < 4; y++)
                    acc[x][y] = fmaf(a[x], b[y], acc[x][y]);
        }
        __syncthreads();
    }
    float* outp = (mode == 0) ? g_A : g_Bt;
    #pragma unroll
    for (int x = 0; x < 4; x++)
        #pragma unroll
        for (int y = 0; y < 4; y++)
            outp[(size_t)(i0 + ty*4 + x) * MM + j0 + tx*4 + y] = acc[x][y];
}

// ---------------- big GEMM 1: hB = tanh(z @ Bt + c), ldj partials ----------------
// 128x128x16 tiles, 256 threads, 8x8 microtile via fma.rn.f32x2.
// Thread (tx,ty): rows m0+ty*8+i, col pairs n0 + 32*jp + 2*tx (+0/1).
__global__ void __launch_bounds__(256, 2) gemm1_kernel(const float* __restrict__ z,
                                                       const float* __restrict__ c,
                                                       float* __restrict__ ldj) {
    __shared__ float As2[16][260];   // A values duplicated: As2[k][2m]=As2[k][2m+1]
    __shared__ float Bs [16][132];
    int tid = threadIdx.x;
    int tx = tid & 15, ty = tid >> 4;
    int n0 = blockIdx.x * 128;
    int m0 = blockIdx.y * 128;
    u64 acc[8][4];
    #pragma unroll
    for (int i = 0; i < 8; i++)
        #pragma unroll
        for (int jp = 0; jp < 4; jp++) acc[i][jp] = 0ull;

    for (int kt = 0; kt < 32; kt++) {
        #pragma unroll
        for (int l = 0; l < 2; l++) {     // A tile = z, duplicated stores
            int idx = tid + l * 256;
            int m = idx >> 2, kq = idx & 3;
            float4 av = *(const float4*)&z[(size_t)(m0 + m) * ZS + kt * 16 + kq * 4];
            *(float2*)&As2[kq*4+0][2*m] = make_float2(av.x, av.x);
            *(float2*)&As2[kq*4+1][2*m] = make_float2(av.y, av.y);
            *(float2*)&As2[kq*4+2][2*m] = make_float2(av.z, av.z);
            *(float2*)&As2[kq*4+3][2*m] = make_float2(av.w, av.w);
        }
        #pragma unroll
        for (int l = 0; l < 2; l++) {     // B tile = Bt rows
            int idx = tid + l * 256;
            int kr = idx >> 5, nq = idx & 31;
            float4 bv = *(const float4*)&g_Bt[(size_t)(kt * 16 + kr) * MM + n0 + nq * 4];
            *(float4*)&Bs[kr][nq * 4] = bv;
        }
        __syncthreads();
        #pragma unroll
        for (int kk = 0; kk < 16; kk++) {
            u64 a[8], b[4];
            #pragma unroll
            for (int i = 0; i < 8; i++)  a[i]  = *(const u64*)&As2[kk][2 * (ty * 8 + i)];
            #pragma unroll
            for (int jp = 0; jp < 4; jp++) b[jp] = *(const u64*)&Bs[kk][32 * jp + 2 * tx];
            #pragma unroll
            for (int i = 0; i < 8; i++)
                #pragma unroll
                for (int jp = 0; jp < 4; jp++)
                    acc[i][jp] = fma2(a[i], b[jp], acc[i][jp]);
        }
        __syncthreads();
    }

    float cc[8], rr[8];
    #pragma unroll
    for (int jp = 0; jp < 4; jp++) {
        int col = n0 + 32 * jp + 2 * tx;
        cc[2*jp] = c[col];       cc[2*jp+1] = c[col + 1];
        rr[2*jp] = g_rrii[col];  rr[2*jp+1] = g_rrii[col + 1];
    }
    #pragma unroll
    for (int i = 0; i < 8; i++) {
        int row = m0 + ty * 8 + i;
        float s = 0.f;
        #pragma unroll
        for (int jp = 0; jp < 4; jp++) {
            float v0, v1; unpack2(acc[i][jp], v0, v1);
            int col = n0 + 32 * jp + 2 * tx;
            float h0 = tanhf(v0 + cc[2*jp]);
            float h1 = tanhf(v1 + cc[2*jp+1]);
            *(float2*)&g_hB[(size_t)row * MM + col] = make_float2(h0, h1);
            float d0 = 1.f - h0 * h0;
            float d1 = 1.f - h1 * h1;
            s += __logf(fabsf(fmaf(d0, rr[2*jp],   1.f)));
            s += __logf(fabsf(fmaf(d1, rr[2*jp+1], 1.f)));
        }
        s += __shfl_xor_sync(0xffffffffu, s, 8);
        s += __shfl_xor_sync(0xffffffffu, s, 4);
        s += __shfl_xor_sync(0xffffffffu, s, 2);
        s += __shfl_xor_sync(0xffffffffu, s, 1);
        if (tx == 0) atomicAdd(&ldj[row], s);
    }
}

// ---------------- big GEMM 2: z_out = hB @ A^T + z ----------------
__global__ void __launch_bounds__(256, 2) gemm2_kernel(const float* __restrict__ z,
                                                       float* __restrict__ out) {
    __shared__ float As2[16][260];
    __shared__ float Bs [16][132];
    int tid = threadIdx.x;
    int tx = tid & 15, ty = tid >> 4;
    int n0 = blockIdx.x * 128;
    int m0 = blockIdx.y * 128;
    u64 acc[8][4];
    #pragma unroll
    for (int i = 0; i < 8; i++)
        #pragma unroll
        for (int jp = 0; jp < 4; jp++) acc[i][jp] = 0ull;

    for (int kt = 0; kt < 32; kt++) {
        #pragma unroll
        for (int l = 0; l < 2; l++) {     // A tile = hB, duplicated
            int idx = tid + l * 256;
            int m = idx >> 2, kq = idx & 3;
            float4 av = *(const float4*)&g_hB[(size_t)(m0 + m) * MM + kt * 16 + kq * 4];
            *(float2*)&As2[kq*4+0][2*m] = make_float2(av.x, av.x);
            *(float2*)&As2[kq*4+1][2*m] = make_float2(av.y, av.y);
            *(float2*)&As2[kq*4+2][2*m] = make_float2(av.z, av.z);
            *(float2*)&As2[kq*4+3][2*m] = make_float2(av.w, av.w);
        }
        #pragma unroll
        for (int l = 0; l < 2; l++) {     // B tile: B[mk][n] = g_A[n0+n][mk] (transposed)
            int idx = tid + l * 256;
            int n = idx >> 2, q = idx & 3;
            float4 t = *(const float4*)&g_A[(size_t)(n0 + n) * MM + kt * 16 + q * 4];
            Bs[q*4+0][n] = t.x; Bs[q*4+1][n] = t.y;
            Bs[q*4+2][n] = t.z; Bs[q*4+3][n] = t.w;
        }
        __syncthreads();
        #pragma unroll
        for (int kk = 0; kk < 16; kk++) {
            u64 a[8], b[4];
            #pragma unroll
            for (int i = 0; i < 8; i++)  a[i]  = *(const u64*)&As2[kk][2 * (ty * 8 + i)];
            #pragma unroll
            for (int jp = 0; jp < 4; jp++) b[jp] = *(const u64*)&Bs[kk][32 * jp + 2 * tx];
            #pragma unroll
            for (int i = 0; i < 8; i++)
                #pragma unroll
                for (int jp = 0; jp < 4; jp++)
                    acc[i][jp] = fma2(a[i], b[jp], acc[i][jp]);
        }
        __syncthreads();
    }

    #pragma unroll
    for (int i = 0; i < 8; i++) {
        int row = m0 + ty * 8 + i;
        #pragma unroll
        for (int jp = 0; jp < 4; jp++) {
            float v0, v1; unpack2(acc[i][jp], v0, v1);
            int col = n0 + 32 * jp + 2 * tx;
            float2 zp = *(const float2*)&z[(size_t)row * ZS + col];
            *(float2*)&out[(size_t)row * ZS + col] = make_float2(v0 + zp.x, v1 + zp.y);
        }
    }
}

// ---------------- launch ----------------
extern "C" void kernel_launch(void* const* d_in, const int* in_sizes, int n_in,
                              void* d_out, int out_size) {
    const float* z      = (const float*)d_in[0];
    const float* v      = (const float*)d_in[1];
    const float* Rs     = (const float*)d_in[2];
    const float* r2diag = (const float*)d_in[3];
    const float* c      = (const float*)d_in[4];
    float* out = (float*)d_out;
    float* ldj = out + (size_t)NB * ZS;   // output layout: [z_out (65536x512), ldj (65536)]

    init_kernel<<<NB / 256, 256>>>(Rs, r2diag, ldj);
    normalize_kernel<<<HHN, 256>>>(v);
    scan_kernel<<<64, 256>>>();
    small_gemm_kernel<<<dim3(8, 8, 2), 256>>>(Rs, r2diag);
    gemm1_kernel<<<dim3(4, 512), 256>>>(z, c, ldj);
    gemm2_kernel<<<dim3(4, 512), 256>>>(z, out);
}

// round 6
// speedup vs baseline: 1.9496x; 1.9496x over previous
#include <cuda_runtime.h>
#include <cuda_bf16.h>
#include <cstdint>

#define ZS 512
#define MM 512
#define HHN 511
#define NB 65536
typedef __nv_bfloat16 bf16;

__device__ float g_vn[HHN * ZS];
__device__ float g_q [ZS * MM];
__device__ float g_rrii[MM];
__device__ bf16 g_Ahi[ZS * MM],  g_Alo[ZS * MM];      // A[z][m]
__device__ bf16 g_Bthi[MM * ZS], g_Btlo[MM * ZS];     // Bt^T[m][z]
__device__ bf16 g_zhi[(size_t)NB * ZS], g_zlo[(size_t)NB * ZS];
__device__ bf16 g_hbhi[(size_t)NB * MM], g_hblo[(size_t)NB * MM];

__device__ __forceinline__ uint32_t smem_u32(const void* p) {
    uint32_t a;
    asm("{ .reg .u64 t; cvta.to.shared.u64 t, %1; cvt.u32.u64 %0, t; }" : "=r"(a) : "l"(p));
    return a;
}
__device__ __forceinline__ void cpa16(uint32_t s, const void* g) {
    asm volatile("cp.async.cg.shared.global [%0], [%1], 16;" :: "r"(s), "l"(g) : "memory");
}
#define CP_COMMIT() asm volatile("cp.async.commit_group;" ::: "memory")
#define CP_WAIT1()  asm volatile("cp.async.wait_group 1;" ::: "memory")

__device__ __forceinline__ void ldsm4(uint32_t addr, uint32_t* r) {
    asm volatile("ldmatrix.sync.aligned.m8n8.x4.shared.b16 {%0,%1,%2,%3}, [%4];"
        : "=r"(r[0]), "=r"(r[1]), "=r"(r[2]), "=r"(r[3]) : "r"(addr));
}
__device__ __forceinline__ void mma16816(float* d, const uint32_t* a, const uint32_t* b) {
    asm volatile("mma.sync.aligned.m16n8k16.row.col.f32.bf16.bf16.f32 "
        "{%0,%1,%2,%3}, {%4,%5,%6,%7}, {%8,%9}, {%0,%1,%2,%3};"
        : "+f"(d[0]), "+f"(d[1]), "+f"(d[2]), "+f"(d[3])
        : "r"(a[0]), "r"(a[1]), "r"(a[2]), "r"(a[3]), "r"(b[0]), "r"(b[1]));
}

#define STG 32768
#define SMEM_TOTAL (3 * STG)

// ---------------- prep kernels ----------------
__global__ void init_kernel(const float* __restrict__ Rs, const float* __restrict__ r2diag,
                            float* __restrict__ ldj) {
    int i = blockIdx.x * blockDim.x + threadIdx.x;
    if (i < MM) g_rrii[i] = Rs[(size_t)i * MM + i] * r2diag[i];
    if (i < NB) ldj[i] = 0.f;
}

__global__ void normalize_kernel(const float* __restrict__ v) {
    int row = blockIdx.x, tid = threadIdx.x;
    float a = v[row * ZS + tid], b = v[row * ZS + tid + 256];
    float s = a * a + b * b;
    #pragma unroll
    for (int o = 16; o > 0; o >>= 1) s += __shfl_xor_sync(0xffffffffu, s, o);
    __shared__ float ws[8];
    if ((tid & 31) == 0) ws[tid >> 5] = s;
    __syncthreads();
    float inv = rsqrtf(ws[0]+ws[1]+ws[2]+ws[3]+ws[4]+ws[5]+ws[6]+ws[7]);
    g_vn[row * ZS + tid] = a * inv;
    g_vn[row * ZS + tid + 256] = b * inv;
}

__global__ void __launch_bounds__(256) scan_kernel() {
    __shared__ float sv[2][ZS];
    int tid = threadIdx.x, lane = tid & 31, warp = tid >> 5;
    int row = blockIdx.x * 8 + warp, base = lane * 16;
    float f[16];
    #pragma unroll
    for (int j = 0; j < 16; j++) f[j] = (base + j == row) ? 1.f : 0.f;
    { float2 t = *(const float2*)&g_vn[tid * 2]; sv[0][tid*2] = t.x; sv[0][tid*2+1] = t.y; }
    __syncthreads();
    for (int i = 0; i < HHN; i++) {
        float2 nx; bool pf = (i + 1 < HHN);
        if (pf) nx = *(const float2*)&g_vn[(size_t)(i + 1) * ZS + tid * 2];
        const float4* cv4 = (const float4*)(sv[i & 1] + base);
        float vv[16];
        #pragma unroll
        for (int j4 = 0; j4 < 4; j4++) {
            float4 V = cv4[j4];
            vv[j4*4] = V.x; vv[j4*4+1] = V.y; vv[j4*4+2] = V.z; vv[j4*4+3] = V.w;
        }
        float d0=0,d1=0,d2=0,d3=0;
        #pragma unroll
        for (int j4 = 0; j4 < 4; j4++) {
            d0 = fmaf(f[j4*4+0], vv[j4*4+0], d0); d1 = fmaf(f[j4*4+1], vv[j4*4+1], d1);
            d2 = fmaf(f[j4*4+2], vv[j4*4+2], d2); d3 = fmaf(f[j4*4+3], vv[j4*4+3], d3);
        }
        float dot = (d0+d1)+(d2+d3);
        #pragma unroll
        for (int o = 16; o > 0; o >>= 1) dot += __shfl_xor_sync(0xffffffffu, dot, o);
        dot *= 2.f;
        #pragma unroll
        for (int j = 0; j < 16; j++) f[j] = fmaf(-dot, vv[j], f[j]);
        if (pf) { float* nb = sv[(i+1)&1]; nb[tid*2] = nx.x; nb[tid*2+1] = nx.y; }
        __syncthreads();
    }
    float4* qo = (float4*)&g_q[(size_t)row * ZS + base];
    qo[0] = make_float4(f[0],f[1],f[2],f[3]);   qo[1] = make_float4(f[4],f[5],f[6],f[7]);
    qo[2] = make_float4(f[8],f[9],f[10],f[11]); qo[3] = make_float4(f[12],f[13],f[14],f[15]);
}

// small GEMMs -> bf16 hi/lo. mode0: A=q@r1 -> g_Ahi[z][m]; mode1: (q@r2^T)^T -> g_Bthi[m][z]
__global__ void __launch_bounds__(256) small_gemm_kernel(const float* __restrict__ Rs,
                                                         const float* __restrict__ r2diag) {
    __shared__ float Qs[16][68], Bs[16][68];
    int tid = threadIdx.x, tx = tid & 15, ty = tid >> 4;
    int j0 = blockIdx.x * 64, i0 = blockIdx.y * 64, mode = blockIdx.z;
    float acc[4][4] = {};
    for (int kt = 0; kt < 32; kt++) {
        { int i = tid >> 2, kq = tid & 3;
          float4 qv = *(const float4*)&g_q[(size_t)(i0 + i) * ZS + kt * 16 + kq * 4];
          Qs[kq*4][i]=qv.x; Qs[kq*4+1][i]=qv.y; Qs[kq*4+2][i]=qv.z; Qs[kq*4+3][i]=qv.w; }
        if (mode == 0) {
            int kr = tid >> 4, nq = tid & 15, kg = kt*16 + kr, jg0 = j0 + nq*4;
            float4 bv = *(const float4*)&Rs[(size_t)kg * MM + jg0];
            Bs[kr][nq*4+0] = (kg <= jg0+0) ? bv.x : 0.f; Bs[kr][nq*4+1] = (kg <= jg0+1) ? bv.y : 0.f;
            Bs[kr][nq*4+2] = (kg <= jg0+2) ? bv.z : 0.f; Bs[kr][nq*4+3] = (kg <= jg0+3) ? bv.w : 0.f;
        } else {
            int jj = tid >> 2, kq = tid & 3, jg = j0 + jj;
            float4 rv = *(const float4*)&Rs[(size_t)jg * MM + kt * 16 + kq * 4];
            const float* rp = (const float*)&rv;
            #pragma unroll
            for (int e = 0; e < 4; e++) {
                int kg = kt*16 + kq*4 + e;
                Bs[kq*4+e][jj] = (kg > jg) ? rp[e] : ((kg == jg) ? r2diag[jg] : 0.f);
            }
        }
        __syncthreads();
        #pragma unroll
        for (int kk = 0; kk < 16; kk++) {
            float a[4], b[4];
            #pragma unroll
            for (int e = 0; e < 4; e++) { a[e] = Qs[kk][ty*4+e]; b[e] = Bs[kk][tx*4+e]; }
            #pragma unroll
            for (int x = 0; x < 4; x++)
                #pragma unroll
                for (int y = 0; y < 4; y++) acc[x][y] = fmaf(a[x], b[y], acc[x][y]);
        }
        __syncthreads();
    }
    #pragma unroll
    for (int x = 0; x < 4; x++)
        #pragma unroll
        for (int y = 0; y < 4; y++) {
            int i = i0 + ty*4 + x, j = j0 + tx*4 + y;
            float val = acc[x][y];
            bf16 h = __float2bfloat16_rn(val);
            bf16 l = __float2bfloat16_rn(val - __bfloat162float(h));
            if (mode == 0) { g_Ahi[(size_t)i * MM + j] = h; g_Alo[(size_t)i * MM + j] = l; }
            else           { g_Bthi[(size_t)j * ZS + i] = h; g_Btlo[(size_t)j * ZS + i] = l; }
        }
}

__global__ void zsplit_kernel(const float* __restrict__ z) {
    size_t u = ((size_t)blockIdx.x * 256 + threadIdx.x) * 8;
    const float4* zp = (const float4*)(z + u);
    float4 a = zp[0], b = zp[1];
    float vs[8] = {a.x,a.y,a.z,a.w,b.x,b.y,b.z,b.w};
    bf16 hi[8], lo[8];
    #pragma unroll
    for (int e = 0; e < 8; e++) {
        hi[e] = __float2bfloat16_rn(vs[e]);
        lo[e] = __float2bfloat16_rn(vs[e] - __bfloat162float(hi[e]));
    }
    *(uint4*)&g_zhi[u] = *(uint4*)hi;
    *(uint4*)&g_zlo[u] = *(uint4*)lo;
}

// ---------------- mma.sync mainloop ----------------
// stage layout: op (Ah,Al,Bh,Bl) * 8192B; op: slab(k16) * 4096B; slab: row*32B (16 bf16),
// 16B-half swizzled by row bit2.
__device__ __forceinline__ void load_stage(uint32_t sbuf,
    const bf16* __restrict__ Ah, const bf16* __restrict__ Al,
    const bf16* __restrict__ Bh, const bf16* __restrict__ Bl,
    int m0, int n0, int ch, int tid) {
    #pragma unroll
    for (int q = 0; q < 8; q++) {
        int idx = ((q & 1) << 8) + tid;
        int m = idx >> 2, cc2 = idx & 3;
        int slab = cc2 >> 1, half = cc2 & 1;
        uint32_t dst = sbuf + (q >> 1) * 8192 + slab * 4096 + m * 32
                     + ((half ^ ((m >> 2) & 1)) << 4);
        const bf16* base = (q < 2) ? Ah : (q < 4) ? Al : (q < 6) ? Bh : Bl;
        int row0 = (q < 4) ? m0 : n0;
        cpa16(dst, base + (size_t)(row0 + m) * 512 + ch * 32 + slab * 16 + half * 8);
    }
}

// warp tile 32(m) x 64(n): wm = wid&3, wn = wid>>2. acc[2][8][4].
__device__ __forceinline__ void mainloop(float (&acc)[2][8][4],
    const bf16* __restrict__ Ah, const bf16* __restrict__ Al,
    const bf16* __restrict__ Bh, const bf16* __restrict__ Bl,
    int m0, int n0, uint32_t sb, int tid) {
    int lane = tid & 31, wid = tid >> 5;
    int wm = wid & 3, wn = wid >> 2;
    int arow = (lane & 7) + ((lane >> 3) & 1) * 8;
    int akh  = (lane >> 4) & 1;
    uint32_t aoff = (uint32_t)((wm * 32 + arow) * 32) + ((akh ^ ((arow >> 2) & 1)) << 4);
    int brow = (lane & 7) + ((lane >> 4) & 1) * 8;
    int bkh  = (lane >> 3) & 1;
    uint32_t boff = 16384u + (uint32_t)((wn * 64 + brow) * 32) + ((bkh ^ ((brow >> 2) & 1)) << 4);

    load_stage(sb,       Ah, Al, Bh, Bl, m0, n0, 0, tid); CP_COMMIT();
    load_stage(sb + STG, Ah, Al, Bh, Bl, m0, n0, 1, tid); CP_COMMIT();

    for (int ch = 0; ch < 16; ch++) {
        CP_WAIT1();
        __syncthreads();
        if (ch + 2 < 16)
            load_stage(sb + ((ch + 2) % 3) * STG, Ah, Al, Bh, Bl, m0, n0, ch + 2, tid);
        CP_COMMIT();
        uint32_t st = sb + (ch % 3) * STG;
        #pragma unroll
        for (int slab = 0; slab < 2; slab++) {
            uint32_t sB = st + slab * 4096;
            uint32_t ah[2][4], bb[4][4], xx[2][4];
            ldsm4(sB + aoff,        ah[0]);
            ldsm4(sB + aoff + 512,  ah[1]);
            #pragma unroll
            for (int p = 0; p < 4; p++) ldsm4(sB + boff + p * 512, bb[p]);
            #pragma unroll
            for (int mt = 0; mt < 2; mt++)
                #pragma unroll
                for (int nt = 0; nt < 8; nt++)
                    mma16816(acc[mt][nt], ah[mt], &bb[nt >> 1][(nt & 1) * 2]);
            ldsm4(sB + 8192 + aoff,       xx[0]);
            ldsm4(sB + 8192 + aoff + 512, xx[1]);
            #pragma unroll
            for (int mt = 0; mt < 2; mt++)
                #pragma unroll
                for (int nt = 0; nt < 8; nt++)
                    mma16816(acc[mt][nt], xx[mt], &bb[nt >> 1][(nt & 1) * 2]);
            #pragma unroll
            for (int p = 0; p < 4; p++) ldsm4(sB + 8192 + boff + p * 512, bb[p]);
            #pragma unroll
            for (int mt = 0; mt < 2; mt++)
                #pragma unroll
                for (int nt = 0; nt < 8; nt++)
                    mma16816(acc[mt][nt], ah[mt], &bb[nt >> 1][(nt & 1) * 2]);
        }
    }
}

__device__ __forceinline__ uint32_t pack_hi(float a, float b, float& la, float& lb) {
    bf16 ha = __float2bfloat16_rn(a), hb = __float2bfloat16_rn(b);
    la = a - __bfloat162float(ha); lb = b - __bfloat162float(hb);
    __nv_bfloat162 t; t.x = ha; t.y = hb;
    return *(uint32_t*)&t;
}
__device__ __forceinline__ uint32_t pack2(float a, float b) {
    __nv_bfloat162 t; t.x = __float2bfloat16_rn(a); t.y = __float2bfloat16_rn(b);
    return *(uint32_t*)&t;
}

// GEMM1: hB = tanh(z@Bt + c), ldj, emit hB hi/lo
__global__ void __launch_bounds__(256, 2) gemm1_kernel(const float* __restrict__ c,
                                                       float* __restrict__ ldj) {
    extern __shared__ char smem[];
    uint32_t sb = smem_u32(smem);
    int tid = threadIdx.x, lane = tid & 31, wid = tid >> 5;
    int wm = wid & 3, wn = wid >> 2;
    int n0 = blockIdx.x * 128, m0 = blockIdx.y * 128;
    float acc[2][8][4] = {};
    mainloop(acc, g_zhi, g_zlo, g_Bthi, g_Btlo, m0, n0, sb, tid);

    float cc[16], rr[16];
    #pragma unroll
    for (int nt = 0; nt < 8; nt++) {
        int col = n0 + wn * 64 + nt * 8 + (lane & 3) * 2;
        cc[nt*2] = c[col]; cc[nt*2+1] = c[col+1];
        rr[nt*2] = g_rrii[col]; rr[nt*2+1] = g_rrii[col+1];
    }
    #pragma unroll
    for (int mt = 0; mt < 2; mt++) {
        int row = m0 + wm * 32 + mt * 16 + (lane >> 2);
        float s0 = 0.f, s1 = 0.f;
        #pragma unroll
        for (int nt = 0; nt < 8; nt++) {
            int col = n0 + wn * 64 + nt * 8 + (lane & 3) * 2;
            float h00 = tanhf(acc[mt][nt][0] + cc[nt*2]);
            float h01 = tanhf(acc[mt][nt][1] + cc[nt*2+1]);
            float h10 = tanhf(acc[mt][nt][2] + cc[nt*2]);
            float h11 = tanhf(acc[mt][nt][3] + cc[nt*2+1]);
            float l00, l01, l10, l11;
            uint32_t hp0 = pack_hi(h00, h01, l00, l01);
            uint32_t hp1 = pack_hi(h10, h11, l10, l11);
            *(uint32_t*)&g_hbhi[(size_t)row * MM + col]       = hp0;
            *(uint32_t*)&g_hbhi[(size_t)(row + 8) * MM + col] = hp1;
            *(uint32_t*)&g_hblo[(size_t)row * MM + col]       = pack2(l00, l01);
            *(uint32_t*)&g_hblo[(size_t)(row + 8) * MM + col] = pack2(l10, l11);
            s0 += __logf(fabsf(fmaf(1.f - h00*h00, rr[nt*2],   1.f)));
            s0 += __logf(fabsf(fmaf(1.f - h01*h01, rr[nt*2+1], 1.f)));
            s1 += __logf(fabsf(fmaf(1.f - h10*h10, rr[nt*2],   1.f)));
            s1 += __logf(fabsf(fmaf(1.f - h11*h11, rr[nt*2+1], 1.f)));
        }
        s0 += __shfl_xor_sync(0xffffffffu, s0, 1); s0 += __shfl_xor_sync(0xffffffffu, s0, 2);
        s1 += __shfl_xor_sync(0xffffffffu, s1, 1); s1 += __shfl_xor_sync(0xffffffffu, s1, 2);
        if ((lane & 3) == 0) {
            atomicAdd(&ldj[row], s0);
            atomicAdd(&ldj[row + 8], s1);
        }
    }
}

// GEMM2: out = hB @ A^T + z
__global__ void __launch_bounds__(256, 2) gemm2_kernel(const float* __restrict__ z,
                                                       float* __restrict__ out) {
    extern __shared__ char smem[];
    uint32_t sb = smem_u32(smem);
    int tid = threadIdx.x, lane = tid & 31, wid = tid >> 5;
    int wm = wid & 3, wn = wid >> 2;
    int n0 = blockIdx.x * 128, m0 = blockIdx.y * 128;
    float acc[2][8][4] = {};
    mainloop(acc, g_hbhi, g_hblo, g_Ahi, g_Alo, m0, n0, sb, tid);

    #pragma unroll
    for (int mt = 0; mt < 2; mt++) {
        int row = m0 + wm * 32 + mt * 16 + (lane >> 2);
        #pragma unroll
        for (int nt = 0; nt < 8; nt++) {
            int col = n0 + wn * 64 + nt * 8 + (lane & 3) * 2;
            float2 z0 = *(const float2*)&z[(size_t)row * ZS + col];
            float2 z1 = *(const float2*)&z[(size_t)(row + 8) * ZS + col];
            *(float2*)&out[(size_t)row * ZS + col] =
                make_float2(acc[mt][nt][0] + z0.x, acc[mt][nt][1] + z0.y);
            *(float2*)&out[(size_t)(row + 8) * ZS + col] =
                make_float2(acc[mt][nt][2] + z1.x, acc[mt][nt][3] + z1.y);
        }
    }
}

// ---------------- launch ----------------
extern "C" void kernel_launch(void* const* d_in, const int* in_sizes, int n_in,
                              void* d_out, int out_size) {
    const float* z      = (const float*)d_in[0];
    const float* v      = (const float*)d_in[1];
    const float* Rs     = (const float*)d_in[2];
    const float* r2diag = (const float*)d_in[3];
    const float* c      = (const float*)d_in[4];
    float* out = (float*)d_out;
    float* ldj = out + (size_t)NB * ZS;

    cudaFuncSetAttribute(gemm1_kernel, cudaFuncAttributeMaxDynamicSharedMemorySize, SMEM_TOTAL);
    cudaFuncSetAttribute(gemm2_kernel, cudaFuncAttributeMaxDynamicSharedMemorySize, SMEM_TOTAL);

    init_kernel<<<NB / 256, 256>>>(Rs, r2diag, ldj);
    normalize_kernel<<<HHN, 256>>>(v);
    scan_kernel<<<64, 256>>>();
    small_gemm_kernel<<<dim3(8, 8, 2), 256>>>(Rs, r2diag);
    zsplit_kernel<<<(int)((size_t)NB * ZS / 2048), 256>>>(z);
    gemm1_kernel<<<dim3(4, 512), 256, SMEM_TOTAL>>>(c, ldj);
    gemm2_kernel<<<dim3(4, 512), 256, SMEM_TOTAL>>>(z, out);
}

// round 8
// speedup vs baseline: 2.3656x; 1.2134x over previous
#include <cuda_runtime.h>
#include <cuda_bf16.h>
#include <cstdint>

#define ZS 512
#define MM 512
#define HHN 511
#define NB 65536
typedef __nv_bfloat16 bf16;

__device__ float g_vn[512 * ZS];                      // padded: row 511 = 0
__device__ float g_q [ZS * MM];
__device__ float g_T [128 * 16];                      // WY T (4x4) per 4-block
__device__ float g_rrii[MM];
__device__ bf16 g_Ahi[ZS * MM],  g_Alo[ZS * MM];      // A[z][m]
__device__ bf16 g_Bthi[MM * ZS], g_Btlo[MM * ZS];     // Bt^T[m][z]
__device__ bf16 g_zhi[(size_t)NB * ZS], g_zlo[(size_t)NB * ZS];
__device__ bf16 g_hbhi[(size_t)NB * MM], g_hblo[(size_t)NB * MM];

__device__ __forceinline__ uint32_t smem_u32(const void* p) {
    uint32_t a;
    asm("{ .reg .u64 t; cvta.to.shared.u64 t, %1; cvt.u32.u64 %0, t; }" : "=r"(a) : "l"(p));
    return a;
}
__device__ __forceinline__ void cpa16(uint32_t s, const void* g) {
    asm volatile("cp.async.cg.shared.global [%0], [%1], 16;" :: "r"(s), "l"(g) : "memory");
}
#define CP_COMMIT() asm volatile("cp.async.commit_group;" ::: "memory")
#define CP_WAIT1()  asm volatile("cp.async.wait_group 1;" ::: "memory")

__device__ __forceinline__ void ldsm4(uint32_t addr, uint32_t* r) {
    asm volatile("ldmatrix.sync.aligned.m8n8.x4.shared.b16 {%0,%1,%2,%3}, [%4];"
        : "=r"(r[0]), "=r"(r[1]), "=r"(r[2]), "=r"(r[3]) : "r"(addr));
}
__device__ __forceinline__ void mma16816(float* d, const uint32_t* a, const uint32_t* b) {
    asm volatile("mma.sync.aligned.m16n8k16.row.col.f32.bf16.bf16.f32 "
        "{%0,%1,%2,%3}, {%4,%5,%6,%7}, {%8,%9}, {%0,%1,%2,%3};"
        : "+f"(d[0]), "+f"(d[1]), "+f"(d[2]), "+f"(d[3])
        : "r"(a[0]), "r"(a[1]), "r"(a[2]), "r"(a[3]), "r"(b[0]), "r"(b[1]));
}

#define STG 32768
#define SMEM_TOTAL (3 * STG)

// ---------------- normalize + init (512 blocks x 256 thr) ----------------
__global__ void normalize_kernel(const float* __restrict__ v, const float* __restrict__ Rs,
                                 const float* __restrict__ r2diag, float* __restrict__ ldj) {
    int row = blockIdx.x, tid = threadIdx.x;
    int gidx = blockIdx.x * 256 + tid;
    if (gidx < NB) ldj[gidx] = 0.f;
    if (gidx < MM) g_rrii[gidx] = Rs[(size_t)gidx * MM + gidx] * r2diag[gidx];
    if (row < HHN) {
        float a = v[row * ZS + tid], b = v[row * ZS + tid + 256];
        float s = a * a + b * b;
        #pragma unroll
        for (int o = 16; o > 0; o >>= 1) s += __shfl_xor_sync(0xffffffffu, s, o);
        __shared__ float ws[8];
        if ((tid & 31) == 0) ws[tid >> 5] = s;
        __syncthreads();
        float inv = rsqrtf(ws[0]+ws[1]+ws[2]+ws[3]+ws[4]+ws[5]+ws[6]+ws[7]);
        g_vn[row * ZS + tid] = a * inv;
        g_vn[row * ZS + tid + 256] = b * inv;
    } else if (row == HHN) {
        g_vn[row * ZS + tid] = 0.f;
        g_vn[row * ZS + tid + 256] = 0.f;
    }
}

// ---------------- build WY T (4x4) per block of 4 Householders ----------------
__global__ void tbuild_kernel() {
    __shared__ float cs[4][4];
    int tid = threadIdx.x, w = tid >> 5, lane = tid & 31, b = blockIdx.x;
    const int pi[6] = {0,0,0,1,1,2}, pj[6] = {1,2,3,2,3,3};
    if (w < 6) {
        const float* vi = g_vn + (size_t)(b * 4 + pi[w]) * ZS;
        const float* vj = g_vn + (size_t)(b * 4 + pj[w]) * ZS;
        float s = 0.f;
        #pragma unroll
        for (int t = 0; t < 16; t++) s += vi[lane + 32 * t] * vj[lane + 32 * t];
        #pragma unroll
        for (int o = 16; o > 0; o >>= 1) s += __shfl_xor_sync(0xffffffffu, s, o);
        if (lane == 0) cs[pi[w]][pj[w]] = s;
    }
    __syncthreads();
    if (tid == 0) {
        float T[4][4] = {};
        T[0][0] = T[1][1] = T[2][2] = T[3][3] = 2.f;
        for (int k = 1; k < 4; k++)
            for (int i = 0; i < k; i++) {
                float s = 0.f;
                for (int j = i; j < k; j++) s += T[i][j] * cs[j][k];
                T[i][k] = -2.f * s;
            }
        for (int i = 0; i < 4; i++)
            for (int k = 0; k < 4; k++) g_T[b * 16 + i * 4 + k] = T[i][k];
    }
}

// ---------------- fused: scan (blocks 0..63) + zsplit (blocks 64..) ----------------
// scan: 128 thr, 4 warps x 2 rows; lane owns cols {q*128 + lane*4 + e}.
__global__ void __launch_bounds__(128, 2) scan_zsplit_kernel(const float* __restrict__ z) {
    __shared__ float sv[2][4 * 512];
    __shared__ float Ts[2][16];
    int tid = threadIdx.x;
    if (blockIdx.x >= 64) {   // ---- zsplit ----
        size_t u = (((size_t)(blockIdx.x - 64)) * 128 + tid) * 8;
        const float4* zp = (const float4*)(z + u);
        float4 a = zp[0], b = zp[1];
        float vs[8] = {a.x,a.y,a.z,a.w,b.x,b.y,b.z,b.w};
        bf16 hi[8], lo[8];
        #pragma unroll
        for (int e = 0; e < 8; e++) {
            hi[e] = __float2bfloat16_rn(vs[e]);
            lo[e] = __float2bfloat16_rn(vs[e] - __bfloat162float(hi[e]));
        }
        *(uint4*)&g_zhi[u] = *(uint4*)hi;
        *(uint4*)&g_zlo[u] = *(uint4*)lo;
        return;
    }
    // ---- scan ----
    int lane = tid & 31, warp = tid >> 5;
    int r0 = blockIdx.x * 8 + warp * 2;
    float f0[16], f1[16];
    #pragma unroll
    for (int j = 0; j < 16; j++) {
        int col = (j >> 2) * 128 + lane * 4 + (j & 3);
        f0[j] = (col == r0) ? 1.f : 0.f;
        f1[j] = (col == r0 + 1) ? 1.f : 0.f;
    }
    #pragma unroll
    for (int q = 0; q < 4; q++)
        *(float4*)&sv[0][(q * 128 + tid) * 4] = *(const float4*)&g_vn[(q * 128 + tid) * 4];
    if (tid < 16) Ts[0][tid] = g_T[tid];
    __syncthreads();

    for (int blk = 0; blk < 128; blk++) {
        int cur = blk & 1, nxt = cur ^ 1;
        float4 pf[4]; float tpf = 0.f;
        bool more = (blk + 1 < 128);
        if (more) {
            #pragma unroll
            for (int q = 0; q < 4; q++)
                pf[q] = *(const float4*)&g_vn[(size_t)(blk + 1) * 2048 + (q * 128 + tid) * 4];
            if (tid < 16) tpf = g_T[(blk + 1) * 16 + tid];
        }
        float vv[4][16];
        #pragma unroll
        for (int vb = 0; vb < 4; vb++)
            #pragma unroll
            for (int q = 0; q < 4; q++) {
                float4 t = *(const float4*)&sv[cur][vb * 512 + q * 128 + lane * 4];
                vv[vb][q*4+0] = t.x; vv[vb][q*4+1] = t.y; vv[vb][q*4+2] = t.z; vv[vb][q*4+3] = t.w;
            }
        float d0[4] = {}, d1[4] = {};
        #pragma unroll
        for (int vb = 0; vb < 4; vb++)
            #pragma unroll
            for (int j = 0; j < 16; j++) {
                d0[vb] = fmaf(f0[j], vv[vb][j], d0[vb]);
                d1[vb] = fmaf(f1[j], vv[vb][j], d1[vb]);
            }
        #pragma unroll
        for (int o = 16; o > 0; o >>= 1)
            #pragma unroll
            for (int vb = 0; vb < 4; vb++) {
                d0[vb] += __shfl_xor_sync(0xffffffffu, d0[vb], o);
                d1[vb] += __shfl_xor_sync(0xffffffffu, d1[vb], o);
            }
        float w0[4], w1[4];
        #pragma unroll
        for (int k = 0; k < 4; k++) {
            float s0 = 0.f, s1 = 0.f;
            #pragma unroll
            for (int i = 0; i < 4; i++) {
                if (i <= k) {
                    float t = Ts[cur][i * 4 + k];
                    s0 = fmaf(d0[i], t, s0);
                    s1 = fmaf(d1[i], t, s1);
                }
            }
            w0[k] = s0; w1[k] = s1;
        }
        #pragma unroll
        for (int j = 0; j < 16; j++) {
            float a0 = f0[j], a1 = f1[j];
            #pragma unroll
            for (int vb = 0; vb < 4; vb++) {
                a0 = fmaf(-w0[vb], vv[vb][j], a0);
                a1 = fmaf(-w1[vb], vv[vb][j], a1);
            }
            f0[j] = a0; f1[j] = a1;
        }
        if (more) {
            #pragma unroll
            for (int q = 0; q < 4; q++)
                *(float4*)&sv[nxt][(q * 128 + tid) * 4] = pf[q];
            if (tid < 16) Ts[nxt][tid] = tpf;
        }
        __syncthreads();
    }
    #pragma unroll
    for (int q = 0; q < 4; q++) {
        *(float4*)&g_q[(size_t)r0 * ZS + q * 128 + lane * 4] = make_float4(f0[q*4], f0[q*4+1], f0[q*4+2], f0[q*4+3]);
        *(float4*)&g_q[(size_t)(r0 + 1) * ZS + q * 128 + lane * 4] = make_float4(f1[q*4], f1[q*4+1], f1[q*4+2], f1[q*4+3]);
    }
}

// small GEMMs -> bf16 hi/lo. mode0: A=q@r1 -> g_Ahi[z][m]; mode1: (q@r2^T)^T -> g_Bthi[m][z]
__global__ void __launch_bounds__(256) small_gemm_kernel(const float* __restrict__ Rs,
                                                         const float* __restrict__ r2diag) {
    __shared__ float Qs[16][68], Bs[16][68];
    int tid = threadIdx.x, tx = tid & 15, ty = tid >> 4;
    int j0 = blockIdx.x * 64, i0 = blockIdx.y * 64, mode = blockIdx.z;
    float acc[4][4] = {};
    for (int kt = 0; kt < 32; kt++) {
        { int i = tid >> 2, kq = tid & 3;
          float4 qv = *(const float4*)&g_q[(size_t)(i0 + i) * ZS + kt * 16 + kq * 4];
          Qs[kq*4][i]=qv.x; Qs[kq*4+1][i]=qv.y; Qs[kq*4+2][i]=qv.z; Qs[kq*4+3][i]=qv.w; }
        if (mode == 0) {
            int kr = tid >> 4, nq = tid & 15, kg = kt*16 + kr, jg0 = j0 + nq*4;
            float4 bv = *(const float4*)&Rs[(size_t)kg * MM + jg0];
            Bs[kr][nq*4+0] = (kg <= jg0+0) ? bv.x : 0.f; Bs[kr][nq*4+1] = (kg <= jg0+1) ? bv.y : 0.f;
            Bs[kr][nq*4+2] = (kg <= jg0+2) ? bv.z : 0.f; Bs[kr][nq*4+3] = (kg <= jg0+3) ? bv.w : 0.f;
        } else {
            int jj = tid >> 2, kq = tid & 3, jg = j0 + jj;
            float4 rv = *(const float4*)&Rs[(size_t)jg * MM + kt * 16 + kq * 4];
            const float* rp = (const float*)&rv;
            #pragma unroll
            for (int e = 0; e < 4; e++) {
                int kg = kt*16 + kq*4 + e;
                Bs[kq*4+e][jj] = (kg > jg) ? rp[e] : ((kg == jg) ? r2diag[jg] : 0.f);
            }
        }
        __syncthreads();
        #pragma unroll
        for (int kk = 0; kk < 16; kk++) {
            float a[4], b[4];
            #pragma unroll
            for (int e = 0; e < 4; e++) { a[e] = Qs[kk][ty*4+e]; b[e] = Bs[kk][tx*4+e]; }
            #pragma unroll
            for (int x = 0; x < 4; x++)
                #pragma unroll
                for (int y = 0; y < 4; y++) acc[x][y] = fmaf(a[x], b[y], acc[x][y]);
        }
        __syncthreads();
    }
    #pragma unroll
    for (int x = 0; x < 4; x++)
        #pragma unroll
        for (int y = 0; y < 4; y++) {
            int i = i0 + ty*4 + x, j = j0 + tx*4 + y;
            float val = acc[x][y];
            bf16 h = __float2bfloat16_rn(val);
            bf16 l = __float2bfloat16_rn(val - __bfloat162float(h));
            if (mode == 0) { g_Ahi[(size_t)i * MM + j] = h; g_Alo[(size_t)i * MM + j] = l; }
            else           { g_Bthi[(size_t)j * ZS + i] = h; g_Btlo[(size_t)j * ZS + i] = l; }
        }
}

// ---------------- mma.sync mainloop ----------------
__device__ __forceinline__ void load_stage(uint32_t sbuf,
    const bf16* __restrict__ Ah, const bf16* __restrict__ Al,
    const bf16* __restrict__ Bh, const bf16* __restrict__ Bl,
    int m0, int n0, int ch, int tid) {
    #pragma unroll
    for (int q = 0; q < 8; q++) {
        int idx = ((q & 1) << 8) + tid;
        int m = idx >> 2, cc2 = idx & 3;
        int slab = cc2 >> 1, half = cc2 & 1;
        uint32_t dst = sbuf + (q >> 1) * 8192 + slab * 4096 + m * 32
                     + ((half ^ ((m >> 2) & 1)) << 4);
        const bf16* base = (q < 2) ? Ah : (q < 4) ? Al : (q < 6) ? Bh : Bl;
        int row0 = (q < 4) ? m0 : n0;
        cpa16(dst, base + (size_t)(row0 + m) * 512 + ch * 32 + slab * 16 + half * 8);
    }
}

// warp tile 32(m) x 64(n): wm = wid&3, wn = wid>>2. acc[2][8][4].
__device__ __forceinline__ void mainloop(float (&acc)[2][8][4],
    const bf16* __restrict__ Ah, const bf16* __restrict__ Al,
    const bf16* __restrict__ Bh, const bf16* __restrict__ Bl,
    int m0, int n0, uint32_t sb, int tid) {
    int lane = tid & 31, wid = tid >> 5;
    int wm = wid & 3, wn = wid >> 2;
    int arow = (lane & 7) + ((lane >> 3) & 1) * 8;
    int akh  = (lane >> 4) & 1;
    uint32_t aoff = (uint32_t)((wm * 32 + arow) * 32) + ((akh ^ ((arow >> 2) & 1)) << 4);
    int brow = (lane & 7) + ((lane >> 4) & 1) * 8;
    int bkh  = (lane >> 3) & 1;
    uint32_t boff = 16384u + (uint32_t)((wn * 64 + brow) * 32) + ((bkh ^ ((brow >> 2) & 1)) << 4);

    load_stage(sb,       Ah, Al, Bh, Bl, m0, n0, 0, tid); CP_COMMIT();
    load_stage(sb + STG, Ah, Al, Bh, Bl, m0, n0, 1, tid); CP_COMMIT();

    for (int ch = 0; ch < 16; ch++) {
        CP_WAIT1();
        __syncthreads();
        if (ch + 2 < 16)
            load_stage(sb + ((ch + 2) % 3) * STG, Ah, Al, Bh, Bl, m0, n0, ch + 2, tid);
        CP_COMMIT();
        uint32_t st = sb + (ch % 3) * STG;
        #pragma unroll
        for (int slab = 0; slab < 2; slab++) {
            uint32_t sB = st + slab * 4096;
            uint32_t ah[2][4], al[2][4], bh[4][4], bl[4][4];
            ldsm4(sB + aoff,        ah[0]);
            ldsm4(sB + aoff + 512,  ah[1]);
            #pragma unroll
            for (int p = 0; p < 4; p++) ldsm4(sB + boff + p * 512, bh[p]);
            ldsm4(sB + 8192 + aoff,       al[0]);
            ldsm4(sB + 8192 + aoff + 512, al[1]);
            #pragma unroll
            for (int mt = 0; mt < 2; mt++)
                #pragma unroll
                for (int nt = 0; nt < 8; nt++)
                    mma16816(acc[mt][nt], ah[mt], &bh[nt >> 1][(nt & 1) * 2]);
            #pragma unroll
            for (int p = 0; p < 4; p++) ldsm4(sB + 8192 + boff + p * 512, bl[p]);
            #pragma unroll
            for (int mt = 0; mt < 2; mt++)
                #pragma unroll
                for (int nt = 0; nt < 8; nt++)
                    mma16816(acc[mt][nt], al[mt], &bh[nt >> 1][(nt & 1) * 2]);
            #pragma unroll
            for (int mt = 0; mt < 2; mt++)
                #pragma unroll
                for (int nt = 0; nt < 8; nt++)
                    mma16816(acc[mt][nt], ah[mt], &bl[nt >> 1][(nt & 1) * 2]);
        }
    }
}

__device__ __forceinline__ uint32_t pack_hi(float a, float b, float& la, float& lb) {
    bf16 ha = __float2bfloat16_rn(a), hb = __float2bfloat16_rn(b);
    la = a - __bfloat162float(ha); lb = b - __bfloat162float(hb);
    __nv_bfloat162 t; t.x = ha; t.y = hb;
    return *(uint32_t*)&t;
}
__device__ __forceinline__ uint32_t pack2(float a, float b) {
    __nv_bfloat162 t; t.x = __float2bfloat16_rn(a); t.y = __float2bfloat16_rn(b);
    return *(uint32_t*)&t;
}

// GEMM1: hB = tanh(z@Bt + c), ldj, emit hB hi/lo
__global__ void __launch_bounds__(256, 2) gemm1_kernel(const float* __restrict__ c,
                                                       float* __restrict__ ldj) {
    extern __shared__ char smem[];
    uint32_t sb = smem_u32(smem);
    int tid = threadIdx.x, lane = tid & 31, wid = tid >> 5;
    int wm = wid & 3, wn = wid >> 2;
    int n0 = blockIdx.x * 128, m0 = blockIdx.y * 128;
    float acc[2][8][4] = {};
    mainloop(acc, g_zhi, g_zlo, g_Bthi, g_Btlo, m0, n0, sb, tid);

    float cc[16], rr[16];
    #pragma unroll
    for (int nt = 0; nt < 8; nt++) {
        int col = n0 + wn * 64 + nt * 8 + (lane & 3) * 2;
        cc[nt*2] = c[col]; cc[nt*2+1] = c[col+1];
        rr[nt*2] = g_rrii[col]; rr[nt*2+1] = g_rrii[col+1];
    }
    #pragma unroll
    for (int mt = 0; mt < 2; mt++) {
        int row = m0 + wm * 32 + mt * 16 + (lane >> 2);
        float s0 = 0.f, s1 = 0.f;
        #pragma unroll
        for (int nt = 0; nt < 8; nt++) {
            int col = n0 + wn * 64 + nt * 8 + (lane & 3) * 2;
            float h00 = tanhf(acc[mt][nt][0] + cc[nt*2]);
            float h01 = tanhf(acc[mt][nt][1] + cc[nt*2+1]);
            float h10 = tanhf(acc[mt][nt][2] + cc[nt*2]);
            float h11 = tanhf(acc[mt][nt][3] + cc[nt*2+1]);
            float l00, l01, l10, l11;
            uint32_t hp0 = pack_hi(h00, h01, l00, l01);
            uint32_t hp1 = pack_hi(h10, h11, l10, l11);
            *(uint32_t*)&g_hbhi[(size_t)row * MM + col]       = hp0;
            *(uint32_t*)&g_hbhi[(size_t)(row + 8) * MM + col] = hp1;
            *(uint32_t*)&g_hblo[(size_t)row * MM + col]       = pack2(l00, l01);
            *(uint32_t*)&g_hblo[(size_t)(row + 8) * MM + col] = pack2(l10, l11);
            s0 += __logf(fabsf(fmaf(1.f - h00*h00, rr[nt*2],   1.f)));
            s0 += __logf(fabsf(fmaf(1.f - h01*h01, rr[nt*2+1], 1.f)));
            s1 += __logf(fabsf(fmaf(1.f - h10*h10, rr[nt*2],   1.f)));
            s1 += __logf(fabsf(fmaf(1.f - h11*h11, rr[nt*2+1], 1.f)));
        }
        s0 += __shfl_xor_sync(0xffffffffu, s0, 1); s0 += __shfl_xor_sync(0xffffffffu, s0, 2);
        s1 += __shfl_xor_sync(0xffffffffu, s1, 1); s1 += __shfl_xor_sync(0xffffffffu, s1, 2);
        if ((lane & 3) == 0) {
            atomicAdd(&ldj[row], s0);
            atomicAdd(&ldj[row + 8], s1);
        }
    }
}

// GEMM2: out = hB @ A^T + z
__global__ void __launch_bounds__(256, 2) gemm2_kernel(const float* __restrict__ z,
                                                       float* __restrict__ out) {
    extern __shared__ char smem[];
    uint32_t sb = smem_u32(smem);
    int tid = threadIdx.x, lane = tid & 31, wid = tid >> 5;
    int wm = wid & 3, wn = wid >> 2;
    int n0 = blockIdx.x * 128, m0 = blockIdx.y * 128;
    float acc[2][8][4] = {};
    mainloop(acc, g_hbhi, g_hblo, g_Ahi, g_Alo, m0, n0, sb, tid);

    #pragma unroll
    for (int mt = 0; mt < 2; mt++) {
        int row = m0 + wm * 32 + mt * 16 + (lane >> 2);
        #pragma unroll
        for (int nt = 0; nt < 8; nt++) {
            int col = n0 + wn * 64 + nt * 8 + (lane & 3) * 2;
            float2 z0 = *(const float2*)&z[(size_t)row * ZS + col];
            float2 z1 = *(const float2*)&z[(size_t)(row + 8) * ZS + col];
            *(float2*)&out[(size_t)row * ZS + col] =
                make_float2(acc[mt][nt][0] + z0.x, acc[mt][nt][1] + z0.y);
            *(float2*)&out[(size_t)(row + 8) * ZS + col] =
                make_float2(acc[mt][nt][2] + z1.x, acc[mt][nt][3] + z1.y);
        }
    }
}

// ---------------- launch ----------------
extern "C" void kernel_launch(void* const* d_in, const int* in_sizes, int n_in,
                              void* d_out, int out_size) {
    const float* z      = (const float*)d_in[0];
    const float* v      = (const float*)d_in[1];
    const float* Rs     = (const float*)d_in[2];
    const float* r2diag = (const float*)d_in[3];
    const float* c      = (const float*)d_in[4];
    float* out = (float*)d_out;
    float* ldj = out + (size_t)NB * ZS;

    cudaFuncSetAttribute(gemm1_kernel, cudaFuncAttributeMaxDynamicSharedMemorySize, SMEM_TOTAL);
    cudaFuncSetAttribute(gemm2_kernel, cudaFuncAttributeMaxDynamicSharedMemorySize, SMEM_TOTAL);

    normalize_kernel<<<512, 256>>>(v, Rs, r2diag, ldj);
    tbuild_kernel<<<128, 192>>>();
    scan_zsplit_kernel<<<64 + (int)((size_t)NB * ZS / 1024), 128>>>(z);
    small_gemm_kernel<<<dim3(8, 8, 2), 256>>>(Rs, r2diag);
    gemm1_kernel<<<dim3(4, 512), 256, SMEM_TOTAL>>>(c, ldj);
    gemm2_kernel<<<dim3(4, 512), 256, SMEM_TOTAL>>>(z, out);
}

// round 10
// speedup vs baseline: 3.0301x; 1.2809x over previous
#include <cuda_runtime.h>
#include <cuda_fp16.h>
#include <cstdint>

#define ZS 512
#define MM 512
#define HHN 511
#define NB 65536

__device__ float g_vn[512 * ZS];                      // padded: row 511 = 0
__device__ float g_q [ZS * MM];
__device__ float g_T [128 * 16];                      // WY T (4x4) per 4-block
__device__ float g_rrii[MM];
__device__ half g_Af  [ZS * MM];                      // A[z][m] single fp16
__device__ half g_Bthi[MM * ZS], g_Btlo[MM * ZS];     // Bt^T[m][z] fp16 hi/lo
__device__ half g_zhi [(size_t)NB * ZS], g_zlo[(size_t)NB * ZS];
__device__ half g_hbf [(size_t)NB * MM];              // tanh(...) single fp16

__device__ __forceinline__ uint32_t smem_u32(const void* p) {
    uint32_t a;
    asm("{ .reg .u64 t; cvta.to.shared.u64 t, %1; cvt.u32.u64 %0, t; }" : "=r"(a) : "l"(p));
    return a;
}
__device__ __forceinline__ void cpa16(uint32_t s, const void* g) {
    asm volatile("cp.async.cg.shared.global [%0], [%1], 16;" :: "r"(s), "l"(g) : "memory");
}
#define CP_COMMIT() asm volatile("cp.async.commit_group;" ::: "memory")
#define CP_WAIT1()  asm volatile("cp.async.wait_group 1;" ::: "memory")
#define CP_WAIT2()  asm volatile("cp.async.wait_group 2;" ::: "memory")

__device__ __forceinline__ void ldsm4(uint32_t addr, uint32_t* r) {
    asm volatile("ldmatrix.sync.aligned.m8n8.x4.shared.b16 {%0,%1,%2,%3}, [%4];"
        : "=r"(r[0]), "=r"(r[1]), "=r"(r[2]), "=r"(r[3]) : "r"(addr));
}
__device__ __forceinline__ void mma16816(float* d, const uint32_t* a, const uint32_t* b) {
    asm volatile("mma.sync.aligned.m16n8k16.row.col.f32.f16.f16.f32 "
        "{%0,%1,%2,%3}, {%4,%5,%6,%7}, {%8,%9}, {%0,%1,%2,%3};"
        : "+f"(d[0]), "+f"(d[1]), "+f"(d[2]), "+f"(d[3])
        : "r"(a[0]), "r"(a[1]), "r"(a[2]), "r"(a[3]), "r"(b[0]), "r"(b[1]));
}

#define STG1 32768
#define SMEM1 (3 * STG1)
#define STG2 16384
#define SMEM2 (4 * STG2)

// ---------------- normalize + init ----------------
__global__ void normalize_kernel(const float* __restrict__ v, const float* __restrict__ Rs,
                                 const float* __restrict__ r2diag, float* __restrict__ ldj) {
    int row = blockIdx.x, tid = threadIdx.x;
    int gidx = blockIdx.x * 256 + tid;
    if (gidx < NB) ldj[gidx] = 0.f;
    if (gidx < MM) g_rrii[gidx] = Rs[(size_t)gidx * MM + gidx] * r2diag[gidx];
    if (row < HHN) {
        float a = v[row * ZS + tid], b = v[row * ZS + tid + 256];
        float s = a * a + b * b;
        #pragma unroll
        for (int o = 16; o > 0; o >>= 1) s += __shfl_xor_sync(0xffffffffu, s, o);
        __shared__ float ws[8];
        if ((tid & 31) == 0) ws[tid >> 5] = s;
        __syncthreads();
        float inv = rsqrtf(ws[0]+ws[1]+ws[2]+ws[3]+ws[4]+ws[5]+ws[6]+ws[7]);
        g_vn[row * ZS + tid] = a * inv;
        g_vn[row * ZS + tid + 256] = b * inv;
    } else if (row == HHN) {
        g_vn[row * ZS + tid] = 0.f;
        g_vn[row * ZS + tid + 256] = 0.f;
    }
}

// ---------------- WY T build ----------------
__global__ void tbuild_kernel() {
    __shared__ float cs[4][4];
    int tid = threadIdx.x, w = tid >> 5, lane = tid & 31, b = blockIdx.x;
    const int pi[6] = {0,0,0,1,1,2}, pj[6] = {1,2,3,2,3,3};
    if (w < 6) {
        const float* vi = g_vn + (size_t)(b * 4 + pi[w]) * ZS;
        const float* vj = g_vn + (size_t)(b * 4 + pj[w]) * ZS;
        float s = 0.f;
        #pragma unroll
        for (int t = 0; t < 16; t++) s += vi[lane + 32 * t] * vj[lane + 32 * t];
        #pragma unroll
        for (int o = 16; o > 0; o >>= 1) s += __shfl_xor_sync(0xffffffffu, s, o);
        if (lane == 0) cs[pi[w]][pj[w]] = s;
    }
    __syncthreads();
    if (tid == 0) {
        float T[4][4] = {};
        T[0][0] = T[1][1] = T[2][2] = T[3][3] = 2.f;
        for (int k = 1; k < 4; k++)
            for (int i = 0; i < k; i++) {
                float s = 0.f;
                for (int j = i; j < k; j++) s += T[i][j] * cs[j][k];
                T[i][k] = -2.f * s;
            }
        for (int i = 0; i < 4; i++)
            for (int k = 0; k < 4; k++) g_T[b * 16 + i * 4 + k] = T[i][k];
    }
}

// ---------------- fused: scan (blocks 0..63) + zsplit (blocks 64..) ----------------
__global__ void __launch_bounds__(128, 2) scan_zsplit_kernel(const float* __restrict__ z) {
    __shared__ float sv[2][4 * 512];
    __shared__ float Ts[2][16];
    int tid = threadIdx.x;
    if (blockIdx.x >= 64) {   // ---- zsplit: fp32 -> fp16 hi/lo ----
        size_t u = (((size_t)(blockIdx.x - 64)) * 128 + tid) * 8;
        const float4* zp = (const float4*)(z + u);
        float4 a = zp[0], b = zp[1];
        float vs[8] = {a.x,a.y,a.z,a.w,b.x,b.y,b.z,b.w};
        half hi[8], lo[8];
        #pragma unroll
        for (int e = 0; e < 8; e++) {
            hi[e] = __float2half_rn(vs[e]);
            lo[e] = __float2half_rn(vs[e] - __half2float(hi[e]));
        }
        *(uint4*)&g_zhi[u] = *(uint4*)hi;
        *(uint4*)&g_zlo[u] = *(uint4*)lo;
        return;
    }
    // ---- scan ----
    int lane = tid & 31, warp = tid >> 5;
    int r0 = blockIdx.x * 8 + warp * 2;
    float f0[16], f1[16];
    #pragma unroll
    for (int j = 0; j < 16; j++) {
        int col = (j >> 2) * 128 + lane * 4 + (j & 3);
        f0[j] = (col == r0) ? 1.f : 0.f;
        f1[j] = (col == r0 + 1) ? 1.f : 0.f;
    }
    #pragma unroll
    for (int q = 0; q < 4; q++)
        *(float4*)&sv[0][(q * 128 + tid) * 4] = *(const float4*)&g_vn[(q * 128 + tid) * 4];
    if (tid < 16) Ts[0][tid] = g_T[tid];
    __syncthreads();

    for (int blk = 0; blk < 128; blk++) {
        int cur = blk & 1, nxt = cur ^ 1;
        float4 pf[4]; float tpf = 0.f;
        bool more = (blk + 1 < 128);
        if (more) {
            #pragma unroll
            for (int q = 0; q < 4; q++)
                pf[q] = *(const float4*)&g_vn[(size_t)(blk + 1) * 2048 + (q * 128 + tid) * 4];
            if (tid < 16) tpf = g_T[(blk + 1) * 16 + tid];
        }
        float vv[4][16];
        #pragma unroll
        for (int vb = 0; vb < 4; vb++)
            #pragma unroll
            for (int q = 0; q < 4; q++) {
                float4 t = *(const float4*)&sv[cur][vb * 512 + q * 128 + lane * 4];
                vv[vb][q*4+0] = t.x; vv[vb][q*4+1] = t.y; vv[vb][q*4+2] = t.z; vv[vb][q*4+3] = t.w;
            }
        float d0[4] = {}, d1[4] = {};
        #pragma unroll
        for (int vb = 0; vb < 4; vb++)
            #pragma unroll
            for (int j = 0; j < 16; j++) {
                d0[vb] = fmaf(f0[j], vv[vb][j], d0[vb]);
                d1[vb] = fmaf(f1[j], vv[vb][j], d1[vb]);
            }
        #pragma unroll
        for (int o = 16; o > 0; o >>= 1)
            #pragma unroll
            for (int vb = 0; vb < 4; vb++) {
                d0[vb] += __shfl_xor_sync(0xffffffffu, d0[vb], o);
                d1[vb] += __shfl_xor_sync(0xffffffffu, d1[vb], o);
            }
        float w0[4], w1[4];
        #pragma unroll
        for (int k = 0; k < 4; k++) {
            float s0 = 0.f, s1 = 0.f;
            #pragma unroll
            for (int i = 0; i < 4; i++) {
                if (i <= k) {
                    float t = Ts[cur][i * 4 + k];
                    s0 = fmaf(d0[i], t, s0);
                    s1 = fmaf(d1[i], t, s1);
                }
            }
            w0[k] = s0; w1[k] = s1;
        }
        #pragma unroll
        for (int j = 0; j < 16; j++) {
            float a0 = f0[j], a1 = f1[j];
            #pragma unroll
            for (int vb = 0; vb < 4; vb++) {
                a0 = fmaf(-w0[vb], vv[vb][j], a0);
                a1 = fmaf(-w1[vb], vv[vb][j], a1);
            }
            f0[j] = a0; f1[j] = a1;
        }
        if (more) {
            #pragma unroll
            for (int q = 0; q < 4; q++)
                *(float4*)&sv[nxt][(q * 128 + tid) * 4] = pf[q];
            if (tid < 16) Ts[nxt][tid] = tpf;
        }
        __syncthreads();
    }
    #pragma unroll
    for (int q = 0; q < 4; q++) {
        *(float4*)&g_q[(size_t)r0 * ZS + q * 128 + lane * 4] = make_float4(f0[q*4], f0[q*4+1], f0[q*4+2], f0[q*4+3]);
        *(float4*)&g_q[(size_t)(r0 + 1) * ZS + q * 128 + lane * 4] = make_float4(f1[q*4], f1[q*4+1], f1[q*4+2], f1[q*4+3]);
    }
}

// small GEMMs. mode0: A=q@r1 -> g_Af[z][m] (fp16); mode1: (q@r2^T)^T -> g_Bthi/lo[m][z]
__global__ void __launch_bounds__(256) small_gemm_kernel(const float* __restrict__ Rs,
                                                         const float* __restrict__ r2diag) {
    __shared__ float Qs[16][68], Bs[16][68];
    int tid = threadIdx.x, tx = tid & 15, ty = tid >> 4;
    int j0 = blockIdx.x * 64, i0 = blockIdx.y * 64, mode = blockIdx.z;
    float acc[4][4] = {};
    for (int kt = 0; kt < 32; kt++) {
        { int i = tid >> 2, kq = tid & 3;
          float4 qv = *(const float4*)&g_q[(size_t)(i0 + i) * ZS + kt * 16 + kq * 4];
          Qs[kq*4][i]=qv.x; Qs[kq*4+1][i]=qv.y; Qs[kq*4+2][i]=qv.z; Qs[kq*4+3][i]=qv.w; }
        if (mode == 0) {
            int kr = tid >> 4, nq = tid & 15, kg = kt*16 + kr, jg0 = j0 + nq*4;
            float4 bv = *(const float4*)&Rs[(size_t)kg * MM + jg0];
            Bs[kr][nq*4+0] = (kg <= jg0+0) ? bv.x : 0.f; Bs[kr][nq*4+1] = (kg <= jg0+1) ? bv.y : 0.f;
            Bs[kr][nq*4+2] = (kg <= jg0+2) ? bv.z : 0.f; Bs[kr][nq*4+3] = (kg <= jg0+3) ? bv.w : 0.f;
        } else {
            int jj = tid >> 2, kq = tid & 3, jg = j0 + jj;
            float4 rv = *(const float4*)&Rs[(size_t)jg * MM + kt * 16 + kq * 4];
            const float* rp = (const float*)&rv;
            #pragma unroll
            for (int e = 0; e < 4; e++) {
                int kg = kt*16 + kq*4 + e;
                Bs[kq*4+e][jj] = (kg > jg) ? rp[e] : ((kg == jg) ? r2diag[jg] : 0.f);
            }
        }
        __syncthreads();
        #pragma unroll
        for (int kk = 0; kk < 16; kk++) {
            float4 a4 = *(const float4*)&Qs[kk][ty * 4];
            float4 b4 = *(const float4*)&Bs[kk][tx * 4];
            const float a[4] = {a4.x, a4.y, a4.z, a4.w};
            const float b[4] = {b4.x, b4.y, b4.z, b4.w};
            #pragma unroll
            for (int x = 0; x < 4; x++)
                #pragma unroll
                for (int y = 0; y < 4; y++) acc[x][y] = fmaf(a[x], b[y], acc[x][y]);
        }
        __syncthreads();
    }
    #pragma unroll
    for (int x = 0; x < 4; x++)
        #pragma unroll
        for (int y = 0; y < 4; y++) {
            int i = i0 + ty*4 + x, j = j0 + tx*4 + y;
            float val = acc[x][y];
            half h = __float2half_rn(val);
            if (mode == 0) {
                g_Af[(size_t)i * MM + j] = h;
            } else {
                g_Bthi[(size_t)j * ZS + i] = h;
                g_Btlo[(size_t)j * ZS + i] = __float2half_rn(val - __half2float(h));
            }
        }
}

// ---------------- GEMM1 mainloop: 3-pass fp16 split, stage = Zh|Zl|Bh|Bl (32KB) ----------------
__device__ __forceinline__ void load_stage1(uint32_t sbuf,
    const half* __restrict__ Ah, const half* __restrict__ Al,
    const half* __restrict__ Bh, const half* __restrict__ Bl,
    int m0, int n0, int ch, int tid) {
    #pragma unroll
    for (int q = 0; q < 8; q++) {
        int idx = ((q & 1) << 8) + tid;
        int m = idx >> 2, cc2 = idx & 3;
        int slab = cc2 >> 1, hf = cc2 & 1;
        uint32_t dst = sbuf + (q >> 1) * 8192 + slab * 4096 + m * 32
                     + ((hf ^ ((m >> 2) & 1)) << 4);
        const half* base = (q < 2) ? Ah : (q < 4) ? Al : (q < 6) ? Bh : Bl;
        int row0 = (q < 4) ? m0 : n0;
        cpa16(dst, base + (size_t)(row0 + m) * 512 + ch * 32 + slab * 16 + hf * 8);
    }
}

__device__ __forceinline__ void mainloop3(float (&acc)[2][8][4],
    const half* __restrict__ Ah, const half* __restrict__ Al,
    const half* __restrict__ Bh, const half* __restrict__ Bl,
    int m0, int n0, uint32_t sb, int tid) {
    int lane = tid & 31, wid = tid >> 5;
    int wm = wid & 3, wn = wid >> 2;
    int arow = (lane & 7) + ((lane >> 3) & 1) * 8;
    int akh  = (lane >> 4) & 1;
    uint32_t aoff = (uint32_t)((wm * 32 + arow) * 32) + ((akh ^ ((arow >> 2) & 1)) << 4);
    int brow = (lane & 7) + ((lane >> 4) & 1) * 8;
    int bkh  = (lane >> 3) & 1;
    uint32_t boff = 16384u + (uint32_t)((wn * 64 + brow) * 32) + ((bkh ^ ((brow >> 2) & 1)) << 4);

    load_stage1(sb,        Ah, Al, Bh, Bl, m0, n0, 0, tid); CP_COMMIT();
    load_stage1(sb + STG1, Ah, Al, Bh, Bl, m0, n0, 1, tid); CP_COMMIT();

    for (int ch = 0; ch < 16; ch++) {
        CP_WAIT1();
        __syncthreads();
        if (ch + 2 < 16)
            load_stage1(sb + ((ch + 2) % 3) * STG1, Ah, Al, Bh, Bl, m0, n0, ch + 2, tid);
        CP_COMMIT();
        uint32_t st = sb + (ch % 3) * STG1;
        #pragma unroll
        for (int slab = 0; slab < 2; slab++) {
            uint32_t sB = st + slab * 4096;
            uint32_t ah[2][4], al[2][4], bh[4][4], bl[4][4];
            ldsm4(sB + aoff,        ah[0]);
            ldsm4(sB + aoff + 512,  ah[1]);
            #pragma unroll
            for (int p = 0; p < 4; p++) ldsm4(sB + boff + p * 512, bh[p]);
            ldsm4(sB + 8192 + aoff,       al[0]);
            ldsm4(sB + 8192 + aoff + 512, al[1]);
            #pragma unroll
            for (int mt = 0; mt < 2; mt++)
                #pragma unroll
                for (int nt = 0; nt < 8; nt++)
                    mma16816(acc[mt][nt], ah[mt], &bh[nt >> 1][(nt & 1) * 2]);
            #pragma unroll
            for (int p = 0; p < 4; p++) ldsm4(sB + 8192 + boff + p * 512, bl[p]);
            #pragma unroll
            for (int mt = 0; mt < 2; mt++)
                #pragma unroll
                for (int nt = 0; nt < 8; nt++)
                    mma16816(acc[mt][nt], al[mt], &bh[nt >> 1][(nt & 1) * 2]);
            #pragma unroll
            for (int mt = 0; mt < 2; mt++)
                #pragma unroll
                for (int nt = 0; nt < 8; nt++)
                    mma16816(acc[mt][nt], ah[mt], &bl[nt >> 1][(nt & 1) * 2]);
        }
    }
}

// ---------------- GEMM2 mainloop: single-pass fp16, stage = A|B (16KB) ----------------
__device__ __forceinline__ void load_stage2(uint32_t sbuf,
    const half* __restrict__ A, const half* __restrict__ B,
    int m0, int n0, int ch, int tid) {
    #pragma unroll
    for (int q = 0; q < 4; q++) {
        int idx = ((q & 1) << 8) + tid;
        int m = idx >> 2, cc2 = idx & 3;
        int slab = cc2 >> 1, hf = cc2 & 1;
        uint32_t dst = sbuf + (q >> 1) * 8192 + slab * 4096 + m * 32
                     + ((hf ^ ((m >> 2) & 1)) << 4);
        const half* base = (q < 2) ? A : B;
        int row0 = (q < 2) ? m0 : n0;
        cpa16(dst, base + (size_t)(row0 + m) * 512 + ch * 32 + slab * 16 + hf * 8);
    }
}

__device__ __forceinline__ void mainloop1(float (&acc)[2][8][4],
    const half* __restrict__ A, const half* __restrict__ B,
    int m0, int n0, uint32_t sb, int tid) {
    int lane = tid & 31, wid = tid >> 5;
    int wm = wid & 3, wn = wid >> 2;
    int arow = (lane & 7) + ((lane >> 3) & 1) * 8;
    int akh  = (lane >> 4) & 1;
    uint32_t aoff = (uint32_t)((wm * 32 + arow) * 32) + ((akh ^ ((arow >> 2) & 1)) << 4);
    int brow = (lane & 7) + ((lane >> 4) & 1) * 8;
    int bkh  = (lane >> 3) & 1;
    uint32_t boff = 8192u + (uint32_t)((wn * 64 + brow) * 32) + ((bkh ^ ((brow >> 2) & 1)) << 4);

    load_stage2(sb,            A, B, m0, n0, 0, tid); CP_COMMIT();
    load_stage2(sb + STG2,     A, B, m0, n0, 1, tid); CP_COMMIT();
    load_stage2(sb + 2 * STG2, A, B, m0, n0, 2, tid); CP_COMMIT();

    for (int ch = 0; ch < 16; ch++) {
        CP_WAIT2();
        __syncthreads();
        if (ch + 3 < 16) {
            load_stage2(sb + ((ch + 3) & 3) * STG2, A, B, m0, n0, ch + 3, tid);
            CP_COMMIT();
        }
        uint32_t st = sb + (ch & 3) * STG2;
        #pragma unroll
        for (int slab = 0; slab < 2; slab++) {
            uint32_t sB = st + slab * 4096;
            uint32_t ah[2][4], bh[4][4];
            ldsm4(sB + aoff,       ah[0]);
            ldsm4(sB + aoff + 512, ah[1]);
            #pragma unroll
            for (int p = 0; p < 4; p++) ldsm4(sB + boff + p * 512, bh[p]);
            #pragma unroll
            for (int mt = 0; mt < 2; mt++)
                #pragma unroll
                for (int nt = 0; nt < 8; nt++)
                    mma16816(acc[mt][nt], ah[mt], &bh[nt >> 1][(nt & 1) * 2]);
        }
        __syncthreads();
    }
}

// GEMM1: hB = tanh(z@Bt + c), ldj, emit hB fp16
__global__ void __launch_bounds__(256, 2) gemm1_kernel(const float* __restrict__ c,
                                                       float* __restrict__ ldj) {
    extern __shared__ char smem[];
    uint32_t sb = smem_u32(smem);
    int tid = threadIdx.x, lane = tid & 31, wid = tid >> 5;
    int wm = wid & 3, wn = wid >> 2;
    int n0 = blockIdx.x * 128, m0 = blockIdx.y * 128;
    float acc[2][8][4] = {};
    mainloop3(acc, g_zhi, g_zlo, g_Bthi, g_Btlo, m0, n0, sb, tid);

    float cc[16], rr[16];
    #pragma unroll
    for (int nt = 0; nt < 8; nt++) {
        int col = n0 + wn * 64 + nt * 8 + (lane & 3) * 2;
        cc[nt*2] = c[col]; cc[nt*2+1] = c[col+1];
        rr[nt*2] = g_rrii[col]; rr[nt*2+1] = g_rrii[col+1];
    }
    #pragma unroll
    for (int mt = 0; mt < 2; mt++) {
        int row = m0 + wm * 32 + mt * 16 + (lane >> 2);
        float s0 = 0.f, s1 = 0.f;
        #pragma unroll
        for (int nt = 0; nt < 8; nt++) {
            int col = n0 + wn * 64 + nt * 8 + (lane & 3) * 2;
            float h00 = tanhf(acc[mt][nt][0] + cc[nt*2]);
            float h01 = tanhf(acc[mt][nt][1] + cc[nt*2+1]);
            float h10 = tanhf(acc[mt][nt][2] + cc[nt*2]);
            float h11 = tanhf(acc[mt][nt][3] + cc[nt*2+1]);
            *(half2*)&g_hbf[(size_t)row * MM + col]       = __floats2half2_rn(h00, h01);
            *(half2*)&g_hbf[(size_t)(row + 8) * MM + col] = __floats2half2_rn(h10, h11);
            s0 += __logf(fabsf(fmaf(1.f - h00*h00, rr[nt*2],   1.f)));
            s0 += __logf(fabsf(fmaf(1.f - h01*h01, rr[nt*2+1], 1.f)));
            s1 += __logf(fabsf(fmaf(1.f - h10*h10, rr[nt*2],   1.f)));
            s1 += __logf(fabsf(fmaf(1.f - h11*h11, rr[nt*2+1], 1.f)));
        }
        s0 += __shfl_xor_sync(0xffffffffu, s0, 1); s0 += __shfl_xor_sync(0xffffffffu, s0, 2);
        s1 += __shfl_xor_sync(0xffffffffu, s1, 1); s1 += __shfl_xor_sync(0xffffffffu, s1, 2);
        if ((lane & 3) == 0) {
            atomicAdd(&ldj[row], s0);
            atomicAdd(&ldj[row + 8], s1);
        }
    }
}

// GEMM2: out = hB @ A^T + z
__global__ void __launch_bounds__(256, 2) gemm2_kernel(const float* __restrict__ z,
                                                       float* __restrict__ out) {
    extern __shared__ char smem[];
    uint32_t sb = smem_u32(smem);
    int tid = threadIdx.x, lane = tid & 31, wid = tid >> 5;
    int wm = wid & 3, wn = wid >> 2;
    int n0 = blockIdx.x * 128, m0 = blockIdx.y * 128;
    float acc[2][8][4] = {};
    mainloop1(acc, g_hbf, g_Af, m0, n0, sb, tid);

    #pragma unroll
    for (int mt = 0; mt < 2; mt++) {
        int row = m0 + wm * 32 + mt * 16 + (lane >> 2);
        #pragma unroll
        for (int nt = 0; nt < 8; nt++) {
            int col = n0 + wn * 64 + nt * 8 + (lane & 3) * 2;
            float2 z0 = *(const float2*)&z[(size_t)row * ZS + col];
            float2 z1 = *(const float2*)&z[(size_t)(row + 8) * ZS + col];
            *(float2*)&out[(size_t)row * ZS + col] =
                make_float2(acc[mt][nt][0] + z0.x, acc[mt][nt][1] + z0.y);
            *(float2*)&out[(size_t)(row + 8) * ZS + col] =
                make_float2(acc[mt][nt][2] + z1.x, acc[mt][nt][3] + z1.y);
        }
    }
}

// ---------------- launch ----------------
extern "C" void kernel_launch(void* const* d_in, const int* in_sizes, int n_in,
                              void* d_out, int out_size) {
    const float* z      = (const float*)d_in[0];
    const float* v      = (const float*)d_in[1];
    const float* Rs     = (const float*)d_in[2];
    const float* r2diag = (const float*)d_in[3];
    const float* c      = (const float*)d_in[4];
    float* out = (float*)d_out;
    float* ldj = out + (size_t)NB * ZS;

    cudaFuncSetAttribute(gemm1_kernel, cudaFuncAttributeMaxDynamicSharedMemorySize, SMEM1);
    cudaFuncSetAttribute(gemm2_kernel, cudaFuncAttributeMaxDynamicSharedMemorySize, SMEM2);

    normalize_kernel<<<512, 256>>>(v, Rs, r2diag, ldj);
    tbuild_kernel<<<128, 192>>>();
    scan_zsplit_kernel<<<64 + (int)((size_t)NB * ZS / 1024), 128>>>(z);
    small_gemm_kernel<<<dim3(8, 8, 2), 256>>>(Rs, r2diag);
    gemm1_kernel<<<dim3(4, 512), 256, SMEM1>>>(c, ldj);
    gemm2_kernel<<<dim3(4, 512), 256, SMEM2>>>(z, out);
}